// round 10
// baseline (speedup 1.0000x reference)
#include <cuda_runtime.h>

// GroupEmbedding: out[b,g,d] = sum_f x[b, g*8+f] * W[g,f,d] + bias[g,d],
// zeroed where masked_group_idx[b] == g.
// B=8192, NF=128, G=16, F=8, D=512. Output 256MB fp32 -> HBM-write-bound.
//
// R10 = R9 champion (g-fastest grid, TB=32, .cs stores, register pack2,
//       unroll 2) with ONE change: d2 -> d4 thread layout.
// 256 thr = (half, d4): thread owns 4 columns, STG.128, 2 b-rows/iter.
// Halves issue slots + pack2 ALU per stored byte (issue was 50.3%).
// R7/R8 tested this layout only with confounds (LDS operands / unroll 4);
// this is the clean isolation.

#define B_DIM  8192
#define NF_DIM 128
#define G_DIM  16
#define F_DIM  8
#define D_DIM  512
#define TB     32    // b-values per block
#define TPB    256

__device__ __forceinline__ unsigned long long fma2(unsigned long long a,
                                                   unsigned long long b,
                                                   unsigned long long c) {
    unsigned long long d;
    asm("fma.rn.f32x2 %0, %1, %2, %3;" : "=l"(d) : "l"(a), "l"(b), "l"(c));
    return d;
}

__device__ __forceinline__ unsigned long long pack2(float x) {
    unsigned long long r;
    asm("mov.b64 %0, {%1, %1};" : "=l"(r) : "r"(__float_as_uint(x)));
    return r;
}

union F4U {
    float4 v;
    struct { unsigned long long lo, hi; } u;
};

__global__ __launch_bounds__(TPB, 5) void ge_kernel(
    const float* __restrict__ x, const float* __restrict__ W,
    const float* __restrict__ bias, const int* __restrict__ mg,
    float* __restrict__ out)
{
    __shared__ float4 sx[TB * 2];   // x[b0+t, g*8 .. g*8+8) as 2 float4 per t
    __shared__ int    smask[TB];
    __shared__ int    sflag;        // 1 if masked_group_idx is int64

    const int g    = blockIdx.x;    // g fastest -> wave writes dense region
    const int b0   = blockIdx.y * TB;
    const int d4   = threadIdx.x & 127;   // column group: 4*d4 .. 4*d4+3
    const int half = threadIdx.x >> 7;    // row parity within iteration

    if (threadIdx.x == 0) sflag = 1;
    __syncthreads();

    // ---- Mask-dtype vote on the FIRST 128 ints (same data for all blocks,
    //      L2-hot). int64: hi==0 && lo<16 for all 64 pairs; int32: a "hi"
    //      slot is a random group id, nonzero w.p. 15/16 -> FP ~16^-64.
    if (threadIdx.x < 64) {
        int2 p = reinterpret_cast<const int2*>(mg)[threadIdx.x];
        if (p.y != 0 || ((unsigned)p.x) >= 16u) sflag = 0;  // benign race
    }

    // ---- Stage x tile: threads 0..63, one float4 each (full MLP). ----
    if (threadIdx.x < TB * 2) {
        const int row = threadIdx.x >> 1;
        const int h   = threadIdx.x & 1;
        sx[threadIdx.x] = *reinterpret_cast<const float4*>(
            x + (size_t)(b0 + row) * NF_DIM + g * F_DIM + h * 4);
    }

    // ---- Preload W[g, :, 4*d4 .. 4*d4+3] (8 x float4 = 32 regs) + bias. ----
    F4U w[F_DIM];
    #pragma unroll
    for (int f = 0; f < F_DIM; ++f)
        w[f].v = *reinterpret_cast<const float4*>(
            W + (size_t)(g * F_DIM + f) * D_DIM + d4 * 4);
    F4U bb;
    bb.v = *reinterpret_cast<const float4*>(bias + (size_t)g * D_DIM + d4 * 4);

    __syncthreads();                 // sflag + sx visible

    // ---- Stage masks (needs sflag). ----
    if (threadIdx.x < TB) {
        const int b = b0 + threadIdx.x;
        smask[threadIdx.x] = sflag ? mg[2 * b] : mg[b];
    }
    __syncthreads();

    // This thread's store pointer: row (b0 + half), advance 2 rows per iter.
    float4* outp = reinterpret_cast<float4*>(
        out + ((size_t)(b0 + half) * G_DIM + g) * D_DIM) + d4;
    const size_t ostride2 = (size_t)2 * G_DIM * D_DIM / 4;  // 2 b-rows, float4

    #pragma unroll 2
    for (int t = 0; t < TB / 2; ++t) {
        const int r = 2 * t + half;          // row within tile
        const float4 xa = sx[2 * r];
        const float4 xb = sx[2 * r + 1];
        const int    m  = smask[r];

        F4U acc;
        acc.u.lo = bb.u.lo;
        acc.u.hi = bb.u.hi;
        const float xf[F_DIM] = {xa.x, xa.y, xa.z, xa.w, xb.x, xb.y, xb.z, xb.w};
        #pragma unroll
        for (int f = 0; f < F_DIM; ++f) {
            unsigned long long xs = pack2(xf[f]);     // register MOV, cheap
            acc.u.lo = fma2(xs, w[f].u.lo, acc.u.lo); // d pair (0,1)
            acc.u.hi = fma2(xs, w[f].u.hi, acc.u.hi); // d pair (2,3)
        }

        if (m == g) acc.v = make_float4(0.f, 0.f, 0.f, 0.f);

        // Streaming store: output (256MB) is write-once, don't thrash L2.
        __stcs(outp, acc.v);
        outp += ostride2;
    }
}

extern "C" void kernel_launch(void* const* d_in, const int* in_sizes, int n_in,
                              void* d_out, int out_size) {
    const float* x    = (const float*)d_in[0];
    const float* W    = (const float*)d_in[1];
    const float* bias = (const float*)d_in[2];
    // d_in[3] = group_idx: identity arange(G*F).reshape(G,F) -> ignored.
    const int*   mg   = (const int*)d_in[4];
    float*       out  = (float*)d_out;

    dim3 grid(G_DIM, B_DIM / TB);   // g fastest: dense concurrent write region
    ge_kernel<<<grid, TPB>>>(x, W, bias, mg, out);
}

// round 12
// speedup vs baseline: 1.5546x; 1.5546x over previous
#include <cuda_runtime.h>

// GroupEmbedding: out[b,g,d] = sum_f x[b, g*8+f] * W[g,f,d] + bias[g,d],
// zeroed where masked_group_idx[b] == g.
// B=8192, NF=128, G=16, F=8, D=512. Output 256MB fp32 -> HBM-write-bound.
//
// R11 = R9 champion (g-fastest grid, TB=32, d2 layout/STG.64, register
//       pack2, unroll 2) with ONE change: .cs streaming stores -> default
//       .wb writeback. A wave's live write footprint (~47MB) fits L2
//       (126MB); .wb batches dirty-line eviction into large sequential
//       victim streams. Store-shape axis closed: STG.128 convicted (R10:
//       L1tex 81%, 72us), d2/STG.64 is final.

#define B_DIM  8192
#define NF_DIM 128
#define G_DIM  16
#define F_DIM  8
#define D_DIM  512
#define TB     32    // b-values per block
#define TPB    256

__device__ __forceinline__ unsigned long long fma2(unsigned long long a,
                                                   unsigned long long b,
                                                   unsigned long long c) {
    unsigned long long d;
    asm("fma.rn.f32x2 %0, %1, %2, %3;" : "=l"(d) : "l"(a), "l"(b), "l"(c));
    return d;
}

__device__ __forceinline__ unsigned long long pack2(float x) {
    unsigned long long r;
    asm("mov.b64 %0, {%1, %1};" : "=l"(r) : "r"(__float_as_uint(x)));
    return r;
}

union U2 {
    float2 v;
    unsigned long long u;
};

__global__ __launch_bounds__(TPB, 5) void ge_kernel(
    const float* __restrict__ x, const float* __restrict__ W,
    const float* __restrict__ bias, const int* __restrict__ mg,
    float* __restrict__ out)
{
    __shared__ float4 sx[TB * 2];   // x[b0+t, g*8 .. g*8+8) as 2 float4 per t
    __shared__ int    smask[TB];
    __shared__ int    sflag;        // 1 if masked_group_idx is int64

    const int g  = blockIdx.x;      // g fastest -> wave writes dense region
    const int b0 = blockIdx.y * TB;
    const int d2 = threadIdx.x;     // 0..255, owns out[.., g, 2*d2, 2*d2+1]

    if (threadIdx.x == 0) sflag = 1;
    __syncthreads();

    // ---- Mask-dtype vote on the FIRST 128 ints (same data for all blocks,
    //      L2-hot). int64: hi==0 && lo<16 for all 64 pairs; int32: a "hi"
    //      slot is a random group id, nonzero w.p. 15/16 -> FP ~16^-64.
    if (threadIdx.x < 64) {
        int2 p = reinterpret_cast<const int2*>(mg)[threadIdx.x];
        if (p.y != 0 || ((unsigned)p.x) >= 16u) sflag = 0;  // benign race: all write 0
    }

    // ---- Stage x tile: threads 0..63, one float4 each (full MLP). ----
    if (threadIdx.x < TB * 2) {
        const int row  = threadIdx.x >> 1;
        const int half = threadIdx.x & 1;
        sx[threadIdx.x] = *reinterpret_cast<const float4*>(
            x + (size_t)(b0 + row) * NF_DIM + g * F_DIM + half * 4);
    }

    // ---- Preload W[g, :, 2*d2 .. 2*d2+1] (8 x float2 = 16 regs) + bias. ----
    U2 w[F_DIM];
    #pragma unroll
    for (int f = 0; f < F_DIM; ++f)
        w[f].v = *reinterpret_cast<const float2*>(
            W + (size_t)(g * F_DIM + f) * D_DIM + d2 * 2);
    U2 bb;
    bb.v = *reinterpret_cast<const float2*>(bias + (size_t)g * D_DIM + d2 * 2);

    __syncthreads();                 // sflag + sx visible

    // ---- Stage masks (needs sflag). ----
    if (threadIdx.x < TB) {
        const int b = b0 + threadIdx.x;
        smask[threadIdx.x] = sflag ? mg[2 * b] : mg[b];
    }
    __syncthreads();

    float2* outp = reinterpret_cast<float2*>(
        out + ((size_t)b0 * G_DIM + g) * D_DIM) + d2;
    const int ostride = G_DIM * D_DIM / 2;   // float2 stride per b

    #pragma unroll 2
    for (int t = 0; t < TB; ++t) {
        const float4 xa = sx[2 * t];
        const float4 xb = sx[2 * t + 1];
        const int    m  = smask[t];

        U2 acc;
        acc.u = bb.u;
        const float xf[F_DIM] = {xa.x, xa.y, xa.z, xa.w, xb.x, xb.y, xb.z, xb.w};
        #pragma unroll
        for (int f = 0; f < F_DIM; ++f)
            acc.u = fma2(pack2(xf[f]), w[f].u, acc.u);

        if (m == g) acc.v = make_float2(0.f, 0.f);

        // Default .wb store: wave footprint fits L2; dirty lines evict in
        // large sequential victim batches (A/B vs R9's .cs).
        outp[(size_t)t * ostride] = acc.v;
    }
}

extern "C" void kernel_launch(void* const* d_in, const int* in_sizes, int n_in,
                              void* d_out, int out_size) {
    const float* x    = (const float*)d_in[0];
    const float* W    = (const float*)d_in[1];
    const float* bias = (const float*)d_in[2];
    // d_in[3] = group_idx: identity arange(G*F).reshape(G,F) -> ignored.
    const int*   mg   = (const int*)d_in[4];
    float*       out  = (float*)d_out;

    dim3 grid(G_DIM, B_DIM / TB);   // g fastest: dense concurrent write region
    ge_kernel<<<grid, TPB>>>(x, W, bias, mg, out);
}

// round 13
// speedup vs baseline: 1.7098x; 1.0998x over previous
#include <cuda_runtime.h>

// GroupEmbedding: out[b,g,d] = sum_f x[b, g*8+f] * W[g,f,d] + bias[g,d],
// zeroed where masked_group_idx[b] == g.
// B=8192, NF=128, G=16, F=8, D=512. Output 256MB fp32 -> HBM-write-bound.
//
// R12 = R9 champion (g-fastest grid, TB=32, .cs, register pack2, unroll 2,
//       warp-coalesced STG.64) with ONE change: thread = (half, p) owns TWO
//       column-pairs (p and p+128) per row -> the 8 pack2 MOVs + 2 LDS.128
//       + mask + loop overhead amortize over 16B instead of 8B (~24% fewer
//       issue slots/byte; alu was 22.6%, issue 50.3%). Store shape is
//       unchanged: two warp-contiguous 256B STG.64 streams (R10 convicted
//       STG.128; R11 convicted .wb on wall time).

#define B_DIM  8192
#define NF_DIM 128
#define G_DIM  16
#define F_DIM  8
#define D_DIM  512
#define TB     32    // b-values per block
#define TPB    256

__device__ __forceinline__ unsigned long long fma2(unsigned long long a,
                                                   unsigned long long b,
                                                   unsigned long long c) {
    unsigned long long d;
    asm("fma.rn.f32x2 %0, %1, %2, %3;" : "=l"(d) : "l"(a), "l"(b), "l"(c));
    return d;
}

__device__ __forceinline__ unsigned long long pack2(float x) {
    unsigned long long r;
    asm("mov.b64 %0, {%1, %1};" : "=l"(r) : "r"(__float_as_uint(x)));
    return r;
}

union U2 {
    float2 v;
    unsigned long long u;
};

__global__ __launch_bounds__(TPB, 4) void ge_kernel(
    const float* __restrict__ x, const float* __restrict__ W,
    const float* __restrict__ bias, const int* __restrict__ mg,
    float* __restrict__ out)
{
    __shared__ float4 sx[TB * 2];   // x[b0+t, g*8 .. g*8+8) as 2 float4 per t
    __shared__ int    smask[TB];
    __shared__ int    sflag;        // 1 if masked_group_idx is int64

    const int g    = blockIdx.x;    // g fastest -> wave writes dense region
    const int b0   = blockIdx.y * TB;
    const int p    = threadIdx.x & 127;  // pair index: owns pairs p and p+128
    const int half = threadIdx.x >> 7;   // row parity within iteration

    if (threadIdx.x == 0) sflag = 1;
    __syncthreads();

    // ---- Mask-dtype vote on the FIRST 128 ints (same data for all blocks,
    //      L2-hot). int64: hi==0 && lo<16 for all 64 pairs; int32: a "hi"
    //      slot is a random group id, nonzero w.p. 15/16 -> FP ~16^-64.
    if (threadIdx.x < 64) {
        int2 q = reinterpret_cast<const int2*>(mg)[threadIdx.x];
        if (q.y != 0 || ((unsigned)q.x) >= 16u) sflag = 0;  // benign race
    }

    // ---- Stage x tile: threads 0..63, one float4 each (full MLP). ----
    if (threadIdx.x < TB * 2) {
        const int row = threadIdx.x >> 1;
        const int h   = threadIdx.x & 1;
        sx[threadIdx.x] = *reinterpret_cast<const float4*>(
            x + (size_t)(b0 + row) * NF_DIM + g * F_DIM + h * 4);
    }

    // ---- Preload W for both owned pairs (8 f x 2 pairs x float2 = 32 regs)
    //      + 2 bias pairs. ----
    U2 w0[F_DIM], w1[F_DIM];
    #pragma unroll
    for (int f = 0; f < F_DIM; ++f) {
        const float* wrow = W + (size_t)(g * F_DIM + f) * D_DIM;
        w0[f].v = *reinterpret_cast<const float2*>(wrow + p * 2);
        w1[f].v = *reinterpret_cast<const float2*>(wrow + (p + 128) * 2);
    }
    U2 bb0, bb1;
    bb0.v = *reinterpret_cast<const float2*>(bias + (size_t)g * D_DIM + p * 2);
    bb1.v = *reinterpret_cast<const float2*>(bias + (size_t)g * D_DIM + (p + 128) * 2);

    __syncthreads();                 // sflag + sx visible

    // ---- Stage masks (needs sflag). ----
    if (threadIdx.x < TB) {
        const int b = b0 + threadIdx.x;
        smask[threadIdx.x] = sflag ? mg[2 * b] : mg[b];
    }
    __syncthreads();

    // Store pointers for row (b0 + half); advance 2 rows per iteration.
    float2* outp = reinterpret_cast<float2*>(
        out + ((size_t)(b0 + half) * G_DIM + g) * D_DIM) + p;
    const size_t ostride2 = (size_t)2 * G_DIM * D_DIM / 2;  // 2 b-rows, float2

    #pragma unroll 2
    for (int t = 0; t < TB / 2; ++t) {
        const int r = 2 * t + half;          // row within tile
        const float4 xa = sx[2 * r];
        const float4 xb = sx[2 * r + 1];
        const int    m  = smask[r];

        U2 acc0, acc1;
        acc0.u = bb0.u;
        acc1.u = bb1.u;
        const float xf[F_DIM] = {xa.x, xa.y, xa.z, xa.w, xb.x, xb.y, xb.z, xb.w};
        #pragma unroll
        for (int f = 0; f < F_DIM; ++f) {
            const unsigned long long xs = pack2(xf[f]);  // shared by both pairs
            acc0.u = fma2(xs, w0[f].u, acc0.u);
            acc1.u = fma2(xs, w1[f].u, acc1.u);
        }

        if (m == g) {
            acc0.v = make_float2(0.f, 0.f);
            acc1.v = make_float2(0.f, 0.f);
        }

        // Two warp-coalesced 256B STG.64 streams, 1KB apart. Streaming (.cs):
        // output is write-once; inline drain beats deferred .wb on wall time.
        __stcs(outp,       acc0.v);
        __stcs(outp + 128, acc1.v);
        outp += ostride2;
    }
}

extern "C" void kernel_launch(void* const* d_in, const int* in_sizes, int n_in,
                              void* d_out, int out_size) {
    const float* x    = (const float*)d_in[0];
    const float* W    = (const float*)d_in[1];
    const float* bias = (const float*)d_in[2];
    // d_in[3] = group_idx: identity arange(G*F).reshape(G,F) -> ignored.
    const int*   mg   = (const int*)d_in[4];
    float*       out  = (float*)d_out;

    dim3 grid(G_DIM, B_DIM / TB);   // g fastest: dense concurrent write region
    ge_kernel<<<grid, TPB>>>(x, W, bias, mg, out);
}